// round 4
// baseline (speedup 1.0000x reference)
#include <cuda_runtime.h>
#include <cuda_bf16.h>

#define NN 50000
#define NR 16
#define NE 800000
#define NH 64
#define NC 16

// Scratch (no allocations allowed -> __device__ globals)
__device__ float gH1[(size_t)NR * NN * NH];   // 204.8 MB: per-relation transformed nodes, layer 1
__device__ float gX1[(size_t)NN * NH];        // 12.8 MB: layer-1 output (pre-relu accumulator)
__device__ float gH2[(size_t)NR * NN * NC];   // 51.2 MB: per-relation transformed nodes, layer 2
__device__ int   gCnt[NN * NR];               // 3.2 MB: per-(dst, relation) edge counts

__global__ void zero_cnt_kernel() {
    int i = blockIdx.x * blockDim.x + threadIdx.x;
    if (i < NN * NR) gCnt[i] = 0;
}

__global__ void count_kernel(const int* __restrict__ dst, const int* __restrict__ et) {
    int e = blockIdx.x * blockDim.x + threadIdx.x;
    if (e < NE) atomicAdd(&gCnt[dst[e] * NR + et[e]], 1);
}

// H1[r] = X @ W1[r]  (r<16); r==16: X1 = X @ root1 + b1
// Block: 64 nodes x 64 outputs. 256 threads, each computes 16 outputs.
__global__ __launch_bounds__(256) void transform1_kernel(
    const float* __restrict__ x, const float* __restrict__ W1,
    const float* __restrict__ root1, const float* __restrict__ b1) {
    __shared__ float sX[64][65];
    __shared__ float sW[64][64];
    int r  = blockIdx.y;
    int n0 = blockIdx.x * 64;
    const float* Wp = (r < NR) ? (W1 + (size_t)r * NH * NH) : root1;

    for (int i = threadIdx.x; i < NH * NH; i += 256) {
        int row = i >> 6, col = i & 63;
        sW[row][col] = Wp[i];
        int n = n0 + row;
        sX[row][col] = (n < NN) ? x[(size_t)n * NH + col] : 0.f;
    }
    __syncthreads();

    int row  = threadIdx.x & 63;
    int quad = threadIdx.x >> 6;   // 0..3 -> output columns [quad*16, quad*16+16)
    float acc[16];
#pragma unroll
    for (int j = 0; j < 16; j++) acc[j] = 0.f;

#pragma unroll
    for (int k = 0; k < 64; k++) {
        float xv = sX[row][k];
        const float4* wrow = (const float4*)&sW[k][quad * 16];
#pragma unroll
        for (int j4 = 0; j4 < 4; j4++) {
            float4 w = wrow[j4];
            acc[j4 * 4 + 0] += xv * w.x;
            acc[j4 * 4 + 1] += xv * w.y;
            acc[j4 * 4 + 2] += xv * w.z;
            acc[j4 * 4 + 3] += xv * w.w;
        }
    }

    int n = n0 + row;
    if (n >= NN) return;
    if (r < NR) {
        // Streaming store: written once, read once by scatter1 -> keep out of L2 residency.
        float4* o = (float4*)(gH1 + ((size_t)r * NN + n) * NH + quad * 16);
#pragma unroll
        for (int j4 = 0; j4 < 4; j4++)
            __stcs(o + j4, make_float4(acc[j4*4+0], acc[j4*4+1], acc[j4*4+2], acc[j4*4+3]));
    } else {
        float* o = gX1 + (size_t)n * NH + quad * 16;
#pragma unroll
        for (int j = 0; j < 16; j++) o[j] = acc[j] + b1[quad * 16 + j];
    }
}

// Per edge: X1[dst] += H1[et][src] / cnt[dst][et].  16 threads/edge, float4 vector atomics.
// Edge scalars loaded once by the group leader and shfl-broadcast.
__global__ __launch_bounds__(256) void scatter1_kernel(
    const int* __restrict__ src, const int* __restrict__ dst, const int* __restrict__ et) {
    int t = blockIdx.x * 256 + threadIdx.x;
    int e = t >> 4;
    if (e >= NE) return;
    int lane = t & 15;
    int s = 0, d = 0, r = 0;
    float w = 0.f;
    if (lane == 0) {
        s = __ldg(src + e); d = __ldg(dst + e); r = __ldg(et + e);
        w = 1.0f / (float)gCnt[d * NR + r];
    }
    // group of 16 lanes within warp shares one edge
    unsigned base = (threadIdx.x & 16) ? 16u : 0u;
    s = __shfl_sync(0xFFFFFFFFu, s, base);
    d = __shfl_sync(0xFFFFFFFFu, d, base);
    r = __shfl_sync(0xFFFFFFFFu, r, base);
    w = __shfl_sync(0xFFFFFFFFu, w, base);

    float4 v = __ldcs(((const float4*)(gH1 + ((size_t)r * NN + s) * NH)) + lane);
    v.x *= w; v.y *= w; v.z *= w; v.w *= w;
    atomicAdd(((float4*)(gX1 + (size_t)d * NH)) + lane, v);
}

// H2[r] = relu(X1) @ W2[r]; r==16: out = relu(X1) @ root2 + b2
// Block: 64 nodes x 16 outputs. 256 threads, each computes 4 outputs.
__global__ __launch_bounds__(256) void transform2_kernel(
    const float* __restrict__ W2, const float* __restrict__ root2,
    const float* __restrict__ b2, float* __restrict__ out) {
    __shared__ float sX[64][65];
    __shared__ float sW[64][16];
    int r  = blockIdx.y;
    int n0 = blockIdx.x * 64;
    const float* Wp = (r < NR) ? (W2 + (size_t)r * NH * NC) : root2;

    for (int i = threadIdx.x; i < NH * NC; i += 256)
        sW[i >> 4][i & 15] = Wp[i];
    for (int i = threadIdx.x; i < 64 * 64; i += 256) {
        int row = i >> 6, col = i & 63;
        int n = n0 + row;
        float v = (n < NN) ? gX1[(size_t)n * NH + col] : 0.f;
        sX[row][col] = fmaxf(v, 0.f);   // fused ReLU
    }
    __syncthreads();

    int row  = threadIdx.x & 63;
    int part = threadIdx.x >> 6;   // 0..3 -> output columns [part*4, part*4+4)
    float a0 = 0.f, a1 = 0.f, a2 = 0.f, a3 = 0.f;
#pragma unroll
    for (int k = 0; k < 64; k++) {
        float xv = sX[row][k];
        float4 w = *(const float4*)&sW[k][part * 4];
        a0 += xv * w.x; a1 += xv * w.y; a2 += xv * w.z; a3 += xv * w.w;
    }

    int n = n0 + row;
    if (n >= NN) return;
    if (r < NR) {
        __stcs((float4*)(gH2 + ((size_t)r * NN + n) * NC + part * 4),
               make_float4(a0, a1, a2, a3));
    } else {
        const float4 b = *(const float4*)(b2 + part * 4);
        *(float4*)(out + (size_t)n * NC + part * 4) =
            make_float4(a0 + b.x, a1 + b.y, a2 + b.z, a3 + b.w);
    }
}

// Per edge: out[dst] += H2[et][src] / cnt[dst][et].  4 threads/edge, float4 vector atomics.
__global__ __launch_bounds__(256) void scatter2_kernel(
    const int* __restrict__ src, const int* __restrict__ dst, const int* __restrict__ et,
    float* __restrict__ out) {
    int t = blockIdx.x * 256 + threadIdx.x;
    int e = t >> 2;
    if (e >= NE) return;
    int lane = t & 3;
    int s = 0, d = 0, r = 0;
    float w = 0.f;
    if (lane == 0) {
        s = __ldg(src + e); d = __ldg(dst + e); r = __ldg(et + e);
        w = 1.0f / (float)gCnt[d * NR + r];
    }
    unsigned base = threadIdx.x & 28;  // leader lane of each 4-lane group
    s = __shfl_sync(0xFFFFFFFFu, s, base);
    d = __shfl_sync(0xFFFFFFFFu, d, base);
    r = __shfl_sync(0xFFFFFFFFu, r, base);
    w = __shfl_sync(0xFFFFFFFFu, w, base);

    float4 v = __ldcs(((const float4*)(gH2 + ((size_t)r * NN + s) * NC)) + lane);
    v.x *= w; v.y *= w; v.z *= w; v.w *= w;
    atomicAdd(((float4*)(out + (size_t)d * NC)) + lane, v);
}

extern "C" void kernel_launch(void* const* d_in, const int* in_sizes, int n_in,
                              void* d_out, int out_size) {
    const int*   edge_index = (const int*)d_in[0];   // [2, NE]
    const int*   edge_type  = (const int*)d_in[1];   // [NE]
    const float* node_emb   = (const float*)d_in[2]; // [NN, NH]
    const float* W1         = (const float*)d_in[3]; // [NR, NH, NH]
    const float* root1      = (const float*)d_in[4]; // [NH, NH]
    const float* b1         = (const float*)d_in[5]; // [NH]
    const float* W2         = (const float*)d_in[6]; // [NR, NH, NC]
    const float* root2      = (const float*)d_in[7]; // [NH, NC]
    const float* b2         = (const float*)d_in[8]; // [NC]
    float* out = (float*)d_out;                      // [NN, NC]

    const int* src = edge_index;
    const int* dst = edge_index + NE;

    zero_cnt_kernel<<<(NN * NR + 255) / 256, 256>>>();
    count_kernel<<<(NE + 255) / 256, 256>>>(dst, edge_type);

    dim3 tgrid((NN + 63) / 64, NR + 1);
    transform1_kernel<<<tgrid, 256>>>(node_emb, W1, root1, b1);
    scatter1_kernel<<<(NE * 16 + 255) / 256, 256>>>(src, dst, edge_type);
    transform2_kernel<<<tgrid, 256>>>(W2, root2, b2, out);
    scatter2_kernel<<<(NE * 4 + 255) / 256, 256>>>(src, dst, edge_type, out);
}